// round 9
// baseline (speedup 1.0000x reference)
#include <cuda_runtime.h>
#include <math.h>
#include <stdint.h>

// ---------------- problem constants ----------------
// B=64, T_IN=1000, C_IN=4, F=320, K=26, POOL=13, T_CONV=975, T_POOL=75
// H=320, 3H=960, FLAT=48000, D1=2000, D2=301
static const int KSPLIT_D1 = 50;   // 48000 -> chunks of 960

// ---------------- device scratch (no allocations allowed) ----------------
__device__ float g_convout[62400 * 320];        // (B*975, 320) conv+relu
__device__ float g_pooled [4800 * 320];         // (B*75, 320)
__device__ float g_mx     [2 * 4800 * 960];     // x-projections fw|bw, row = b*75+t
__device__ float g_h      [4 * 64 * 320];       // [dir][buf] double-buffered hidden
__device__ float g_mipart [5 * 2 * 64 * 960];   // split-K partials of h@rk
__device__ float g_y      [64 * 48000];         // concat GRU output
__device__ float g_part1  [50 * 64 * 2000];     // dense1 split-K partials
__device__ float g_a1     [64 * 2000];          // dense1 activation

// ---------------- generic tiled fp32 GEMM ----------------
// AMODE: 0 = A[row*lda + k]; 1 = conv im2col view: A[(row/975)*4000 + (row%975)*4 + k]
// EPI:   0 = raw store; 1 = bias + relu; 2 = bias
// kchunk > 0: split-K over blockIdx.z, partial written at C + z*M*ldc (no bias).
template<int BM,int BN,int BK,int TM,int TN,int AMODE,int EPI>
__global__ __launch_bounds__(256)
void gemm_tiled(const float* __restrict__ A, const float* __restrict__ Bm,
                const float* __restrict__ bias, float* __restrict__ C,
                int M, int N, int K, int lda, int ldb, int ldc, int kchunk)
{
    constexpr int TX = BN / TN, TY = BM / TM;
    static_assert(TX * TY == 256, "block must be 256 threads");
    __shared__ float sA[BK][BM + 1];
    __shared__ float sB[BK][BN];

    const int tid = threadIdx.x;
    const int tx = tid % TX, ty = tid / TX;
    const int m0 = blockIdx.y * BM;
    const int n0 = blockIdx.x * BN;

    int kb = 0, ke = K;
    float* Cout = C;
    if (kchunk > 0) {
        kb = blockIdx.z * kchunk;
        ke = min(K, kb + kchunk);
        Cout = C + (size_t)blockIdx.z * (size_t)M * (size_t)ldc;
    }

    float acc[TM][TN];
#pragma unroll
    for (int i = 0; i < TM; i++)
#pragma unroll
        for (int j = 0; j < TN; j++) acc[i][j] = 0.f;

    for (int k0 = kb; k0 < ke; k0 += BK) {
#pragma unroll
        for (int l = 0; l < BM * BK / 256; l++) {
            int idx = tid + l * 256;
            int r = idx / BK, kk = idx % BK;
            int row = m0 + r, k = k0 + kk;
            float v = 0.f;
            if (row < M && k < ke) {
                size_t off;
                if (AMODE == 1) off = (size_t)(row / 975) * 4000 + (size_t)(row % 975) * 4;
                else            off = (size_t)row * (size_t)lda;
                v = A[off + k];
            }
            sA[kk][r] = v;
        }
#pragma unroll
        for (int l = 0; l < BK * BN / 256; l++) {
            int idx = tid + l * 256;
            int kk = idx / BN, c = idx % BN;
            int k = k0 + kk, col = n0 + c;
            sB[kk][c] = (k < ke && col < N) ? Bm[(size_t)k * (size_t)ldb + col] : 0.f;
        }
        __syncthreads();
#pragma unroll
        for (int kk = 0; kk < BK; kk++) {
            float ra[TM], rb[TN];
#pragma unroll
            for (int i = 0; i < TM; i++) ra[i] = sA[kk][ty * TM + i];
#pragma unroll
            for (int j = 0; j < TN; j++) rb[j] = sB[kk][tx * TN + j];
#pragma unroll
            for (int i = 0; i < TM; i++)
#pragma unroll
                for (int j = 0; j < TN; j++) acc[i][j] = fmaf(ra[i], rb[j], acc[i][j]);
        }
        __syncthreads();
    }

#pragma unroll
    for (int i = 0; i < TM; i++) {
        int row = m0 + ty * TM + i;
        if (row >= M) continue;
#pragma unroll
        for (int j = 0; j < TN; j++) {
            int col = n0 + tx * TN + j;
            if (col >= N) continue;
            float v = acc[i][j];
            if (EPI == 1)      v = fmaxf(v + bias[col], 0.f);
            else if (EPI == 2) v = v + bias[col];
            Cout[(size_t)row * (size_t)ldc + col] = v;
        }
    }
}

// ---------------- relu already applied; maxpool over 13 conv rows ----------------
__global__ __launch_bounds__(256)
void pool_kernel(const float* __restrict__ conv, float* __restrict__ pooled)
{
    int idx = blockIdx.x * 256 + threadIdx.x;
    if (idx >= 4800 * 320) return;
    int f = idx % 320;
    int bp = idx / 320;
    int b = bp / 75, p = bp % 75;
    const float* src = conv + ((size_t)(b * 975 + p * 13)) * 320 + f;
    float m = src[0];
#pragma unroll
    for (int q = 1; q < 13; q++) m = fmaxf(m, src[(size_t)q * 320]);
    pooled[idx] = m;
}

// ---------------- GRU step stage 1: mi_part[z][dir] = h_dir @ rk_dir (K split 5x64) ----------------
// grid: (15 col-chunks of 64, 2 dirs, 5 k-splits), 256 threads
__global__ __launch_bounds__(256)
void gru_s1(const float* __restrict__ h_fw, const float* __restrict__ h_bw,
            const float* __restrict__ rk_fw, const float* __restrict__ rk_bw,
            float* __restrict__ mipart)
{
    const int dir = blockIdx.y;
    const float* A  = dir ? h_bw : h_fw;     // (64, 320)
    const float* Bm = dir ? rk_bw : rk_fw;   // (320, 960)
    const int n0 = blockIdx.x * 64;
    const int k0b = blockIdx.z * 64;

    __shared__ float sA[16][65];
    __shared__ float sB[16][64];
    const int tid = threadIdx.x;
    const int tx = tid % 16, ty = tid / 16;

    float acc[4][4];
#pragma unroll
    for (int i = 0; i < 4; i++)
#pragma unroll
        for (int j = 0; j < 4; j++) acc[i][j] = 0.f;

    for (int kt = 0; kt < 4; kt++) {
        int k0 = k0b + kt * 16;
#pragma unroll
        for (int l = 0; l < 4; l++) {
            int idx = tid + l * 256;
            int r = idx / 16, kk = idx % 16;
            sA[kk][r] = A[r * 320 + k0 + kk];
        }
#pragma unroll
        for (int l = 0; l < 4; l++) {
            int idx = tid + l * 256;
            int kk = idx / 64, c = idx % 64;
            sB[kk][c] = Bm[(k0 + kk) * 960 + n0 + c];
        }
        __syncthreads();
#pragma unroll
        for (int kk = 0; kk < 16; kk++) {
            float ra[4], rb[4];
#pragma unroll
            for (int i = 0; i < 4; i++) ra[i] = sA[kk][ty * 4 + i];
#pragma unroll
            for (int j = 0; j < 4; j++) rb[j] = sB[kk][tx * 4 + j];
#pragma unroll
            for (int i = 0; i < 4; i++)
#pragma unroll
                for (int j = 0; j < 4; j++) acc[i][j] = fmaf(ra[i], rb[j], acc[i][j]);
        }
        __syncthreads();
    }

    float* Cp = mipart + ((size_t)(blockIdx.z * 2 + dir) * 64) * 960;
#pragma unroll
    for (int i = 0; i < 4; i++)
#pragma unroll
        for (int j = 0; j < 4; j++)
            Cp[(ty * 4 + i) * 960 + n0 + tx * 4 + j] = acc[i][j];
}

// ---------------- GRU step stage 2: gates (Keras reset_after=True) ----------------
__device__ __forceinline__ float sigmoidf_(float x) { return 1.f / (1.f + expf(-x)); }

__global__ __launch_bounds__(256)
void gru_gate(int s, const float* __restrict__ mipart,
              const float* __restrict__ mx_fw, const float* __restrict__ mx_bw,
              const float* __restrict__ b_fw, const float* __restrict__ b_bw,
              float* __restrict__ h, float* __restrict__ y)
{
    int idx = blockIdx.x * 256 + threadIdx.x;
    if (idx >= 2 * 64 * 320) return;
    int dir = idx / 20480;
    int rem = idx % 20480;        // b*320 + c
    int b = rem / 320, c = rem % 320;
    int t = dir ? (74 - s) : s;

    const float* mx = (dir ? mx_bw : mx_fw) + (size_t)(b * 75 + t) * 960;
    const float* br = (dir ? b_bw : b_fw) + 960;   // recurrent bias row

    float sz = 0.f, sr = 0.f, sh = 0.f;
#pragma unroll
    for (int z = 0; z < 5; z++) {
        const float* p = mipart + ((size_t)(z * 2 + dir) * 64 + b) * 960;
        sz += p[c];
        sr += p[c + 320];
        sh += p[c + 640];
    }

    int cur = s & 1, nxt = cur ^ 1;
    float hold = h[(dir * 2 + cur) * 20480 + rem];

    float zg = sigmoidf_(mx[c]       + sz + br[c]);
    float rg = sigmoidf_(mx[320 + c] + sr + br[320 + c]);
    float hh = sh + br[640 + c];
    float cand = tanhf(mx[640 + c] + rg * hh);
    float hn = zg * hold + (1.f - zg) * cand;

    h[(dir * 2 + nxt) * 20480 + rem] = hn;
    y[(size_t)b * 48000 + (size_t)t * 640 + dir * 320 + c] = hn;
}

// ---------------- dense1 split-K reduce + bias + relu ----------------
__global__ __launch_bounds__(256)
void reduce_relu(const float* __restrict__ part, const float* __restrict__ bias,
                 float* __restrict__ out)
{
    int i = blockIdx.x * 256 + threadIdx.x;
    if (i >= 64 * 2000) return;
    float s = bias[i % 2000];
#pragma unroll 10
    for (int z = 0; z < KSPLIT_D1; z++) s += part[(size_t)z * 128000 + i];
    out[i] = fmaxf(s, 0.f);
}

// ---------------- dense2 + sigmoid ----------------
__global__ void dense2_kernel(const float* __restrict__ a1, const float* __restrict__ w2,
                              const float* __restrict__ b2, float* __restrict__ out)
{
    int n = blockIdx.x * 32 + threadIdx.x;
    int b = blockIdx.y * 8 + threadIdx.y;
    if (n >= 301) return;
    float acc = b2[n];
    const float* arow = a1 + (size_t)b * 2000;
#pragma unroll 4
    for (int k = 0; k < 2000; k++)
        acc = fmaf(arow[k], w2[(size_t)k * 301 + n], acc);
    out[(size_t)b * 301 + n] = 1.f / (1.f + expf(-acc));
}

// ---------------- launcher ----------------
extern "C" void kernel_launch(void* const* d_in, const int* in_sizes, int n_in,
                              void* d_out, int out_size)
{
    const float* inputs = (const float*)d_in[0];
    const float* conv_w = (const float*)d_in[1];
    const float* conv_b = (const float*)d_in[2];
    const float* fw_k   = (const float*)d_in[3];
    const float* fw_rk  = (const float*)d_in[4];
    const float* fw_b   = (const float*)d_in[5];
    const float* bw_k   = (const float*)d_in[6];
    const float* bw_rk  = (const float*)d_in[7];
    const float* bw_b   = (const float*)d_in[8];
    const float* w1     = (const float*)d_in[9];
    const float* b1     = (const float*)d_in[10];
    const float* w2     = (const float*)d_in[11];
    const float* b2     = (const float*)d_in[12];
    float* out = (float*)d_out;

    float *convout, *pooled, *mx, *hbuf, *mipart, *ybuf, *part1, *a1;
    cudaGetSymbolAddress((void**)&convout, g_convout);
    cudaGetSymbolAddress((void**)&pooled,  g_pooled);
    cudaGetSymbolAddress((void**)&mx,      g_mx);
    cudaGetSymbolAddress((void**)&hbuf,    g_h);
    cudaGetSymbolAddress((void**)&mipart,  g_mipart);
    cudaGetSymbolAddress((void**)&ybuf,    g_y);
    cudaGetSymbolAddress((void**)&part1,   g_part1);
    cudaGetSymbolAddress((void**)&a1,      g_a1);

    // 1) Conv1D + bias + relu as GEMM on the stride-4 im2col view:
    //    A[r,kc] = inputs[(r/975)*4000 + (r%975)*4 + kc]; B = conv_w as (104,320)
    gemm_tiled<64,64,16,4,4,1,1><<<dim3(5, 975, 1), 256>>>(
        inputs, conv_w, conv_b, convout, 62400, 320, 104, 4, 320, 320, 0);

    // 2) MaxPool(13)
    pool_kernel<<<(4800 * 320 + 255) / 256, 256>>>(convout, pooled);

    // 3) GRU input projections (with input bias) for both directions
    gemm_tiled<64,128,16,4,8,0,2><<<dim3(8, 75, 1), 256>>>(
        pooled, fw_k, fw_b, mx,               4800, 960, 320, 320, 960, 960, 0);
    gemm_tiled<64,128,16,4,8,0,2><<<dim3(8, 75, 1), 256>>>(
        pooled, bw_k, bw_b, mx + 4800 * 960,  4800, 960, 320, 320, 960, 960, 0);

    // 4) zero hidden state (double-buffered, both directions)
    cudaMemsetAsync(hbuf, 0, 4 * 64 * 320 * sizeof(float));

    // 5) 75 recurrent steps: split-K recurrent GEMM (150 blocks) + fused gates
    for (int s = 0; s < 75; s++) {
        int cur = s & 1;
        gru_s1<<<dim3(15, 2, 5), 256>>>(hbuf + cur * 20480,
                                        hbuf + (2 + cur) * 20480,
                                        fw_rk, bw_rk, mipart);
        gru_gate<<<160, 256>>>(s, mipart, mx, mx + 4800 * 960, fw_b, bw_b, hbuf, ybuf);
    }

    // 6) Dense1 (64,48000)@(48000,2000): 50-way split-K, then reduce+bias+relu
    gemm_tiled<64,128,16,4,8,0,0><<<dim3(16, 1, KSPLIT_D1), 256>>>(
        ybuf, w1, (const float*)0, part1, 64, 2000, 48000, 48000, 2000, 2000, 960);
    reduce_relu<<<(64 * 2000 + 255) / 256, 256>>>(part1, b1, a1);

    // 7) Dense2 + sigmoid
    dense2_kernel<<<dim3(10, 8), dim3(32, 8)>>>(a1, w2, b2, out);

    (void)in_sizes; (void)n_in; (void)out_size;
}

// round 10
// speedup vs baseline: 1.0855x; 1.0855x over previous
#include <cuda_runtime.h>
#include <math.h>
#include <stdint.h>

// ---------------- problem constants ----------------
// B=64, T_IN=1000, C_IN=4, F=320, K=26, POOL=13, T_CONV=975, T_POOL=75
// H=320, 3H=960, FLAT=48000, D1=2000, D2=301
static const int KSPLIT_D1 = 50;   // 48000 -> chunks of 960

// ---------------- device scratch (no allocations allowed) ----------------
__device__ float g_convout[62400 * 320];        // (B*975, 320) conv+relu
__device__ float g_pooled [4800 * 320];         // (B*75, 320)
__device__ float g_mx     [2 * 4800 * 960];     // x-projections fw|bw, row = b*75+t
__device__ float g_hT     [4 * 320 * 64];       // [dir][buf] hidden, TRANSPOSED [k][b]
__device__ float g_y      [64 * 48000];         // concat GRU output
__device__ float g_part1  [50 * 64 * 2000];     // dense1 split-K partials
__device__ float g_a1     [64 * 2000];          // dense1 activation

// ---------------- fp32 GEMM, 8x8 per thread, BK=8, 256 threads ----------------
// AMODE: 0 = A[row*lda + k]; 1 = conv im2col view A[(row/975)*4000 + (row%975)*4 + k]
// EPI:   0 raw, 1 bias+relu, 2 bias
// kchunk>0: split-K over blockIdx.z, partial at C + z*M*ldc (EPI ignored -> raw)
template<int BM,int BN,int AMODE,int EPI>
__global__ __launch_bounds__(256, 2)
void gemm8(const float* __restrict__ A, const float* __restrict__ Bm,
           const float* __restrict__ bias, float* __restrict__ C,
           int M, int N, int K, int lda, int ldb, int ldc, int kchunk)
{
    constexpr int TX = BN / 8, TY = BM / 8;
    static_assert(TX * TY == 256, "need 256 threads");
    __shared__ float sA[8][BM + 4];
    __shared__ float sB[8][BN];

    const int tid = threadIdx.x;
    const int tx = tid % TX, ty = tid / TX;
    const int m0 = blockIdx.y * BM;
    const int n0 = blockIdx.x * BN;

    int kb = 0, ke = K;
    float* Cout = C;
    if (kchunk > 0) {
        kb = blockIdx.z * kchunk;
        ke = kb + kchunk;              // callers guarantee K % kchunk == 0
        Cout = C + (size_t)blockIdx.z * (size_t)M * (size_t)ldc;
    }

    // ---- A loader mapping (row fixed across k-tiles) ----
    int alr, alk;
    if constexpr (BM == 128) { alr = tid >> 1; alk = (tid & 1) * 4; }
    else                     { alr = tid >> 2; alk = (tid & 3) * 2; }
    const int arow = m0 + alr;
    const bool aval = arow < M;
    size_t abase;
    if (AMODE == 1) abase = aval ? (size_t)(arow / 975) * 4000 + (size_t)(arow % 975) * 4 : 0;
    else            abase = aval ? (size_t)arow * (size_t)lda : 0;

    // ---- B loader mapping ----
    const int blk = tid >> 5;            // 0..7
    const int blc = (tid & 31) * 4;      // 0..124
    const bool fullN = (n0 + BN <= N);

    float acc[8][8];
#pragma unroll
    for (int i = 0; i < 8; i++)
#pragma unroll
        for (int j = 0; j < 8; j++) acc[i][j] = 0.f;

    for (int k0 = kb; k0 < ke; k0 += 8) {
        // stage A (transposed)
        if constexpr (BM == 128) {
            float4 v = aval ? *(const float4*)(A + abase + k0 + alk)
                            : make_float4(0.f, 0.f, 0.f, 0.f);
            sA[alk + 0][alr] = v.x; sA[alk + 1][alr] = v.y;
            sA[alk + 2][alr] = v.z; sA[alk + 3][alr] = v.w;
        } else {
            float2 v = aval ? *(const float2*)(A + abase + k0 + alk)
                            : make_float2(0.f, 0.f);
            sA[alk + 0][alr] = v.x; sA[alk + 1][alr] = v.y;
        }
        // stage B
        {
            const float* bp = Bm + (size_t)(k0 + blk) * (size_t)ldb + n0 + blc;
            if (fullN) {
                *(float4*)&sB[blk][blc] = *(const float4*)bp;
                if constexpr (BN == 256)
                    *(float4*)&sB[blk][blc + 128] = *(const float4*)(bp + 128);
            } else {
#pragma unroll
                for (int j = 0; j < 4; j++)
                    sB[blk][blc + j] = (n0 + blc + j < N) ? bp[j] : 0.f;
                if constexpr (BN == 256) {
#pragma unroll
                    for (int j = 0; j < 4; j++)
                        sB[blk][blc + 128 + j] = (n0 + blc + 128 + j < N) ? bp[128 + j] : 0.f;
                }
            }
        }
        __syncthreads();

#pragma unroll
        for (int kk = 0; kk < 8; kk++) {
            float4 a0 = *(const float4*)&sA[kk][ty * 8];
            float4 a1 = *(const float4*)&sA[kk][ty * 8 + 4];
            float4 b0 = *(const float4*)&sB[kk][tx * 8];
            float4 b1 = *(const float4*)&sB[kk][tx * 8 + 4];
            float ra[8] = {a0.x, a0.y, a0.z, a0.w, a1.x, a1.y, a1.z, a1.w};
            float rb[8] = {b0.x, b0.y, b0.z, b0.w, b1.x, b1.y, b1.z, b1.w};
#pragma unroll
            for (int i = 0; i < 8; i++)
#pragma unroll
                for (int j = 0; j < 8; j++)
                    acc[i][j] = fmaf(ra[i], rb[j], acc[i][j]);
        }
        __syncthreads();
    }

#pragma unroll
    for (int i = 0; i < 8; i++) {
        int row = m0 + ty * 8 + i;
        if (row >= M) continue;
        float* crow = Cout + (size_t)row * (size_t)ldc;
#pragma unroll
        for (int j = 0; j < 8; j++) {
            int col = n0 + tx * 8 + j;
            if (col >= N) continue;
            float v = acc[i][j];
            if (kchunk == 0) {
                if (EPI == 1)      v = fmaxf(v + bias[col], 0.f);
                else if (EPI == 2) v = v + bias[col];
            }
            crow[col] = v;
        }
    }
}

// ---------------- maxpool over 13 conv rows ----------------
__global__ __launch_bounds__(256)
void pool_kernel(const float* __restrict__ conv, float* __restrict__ pooled)
{
    int idx = blockIdx.x * 256 + threadIdx.x;
    if (idx >= 4800 * 320) return;
    int f = idx % 320;
    int bp = idx / 320;
    int b = bp / 75, p = bp % 75;
    const float* src = conv + ((size_t)(b * 975 + p * 13)) * 320 + f;
    float m = src[0];
#pragma unroll
    for (int q = 1; q < 13; q++) m = fmaxf(m, src[(size_t)q * 320]);
    pooled[idx] = m;
}

// ---------------- fused GRU step: recurrent GEMM + gates in ONE kernel ----------------
// grid (80, 2): block = (dir, 4 units); 256 threads = {u:4} x {bg:8} x {ks:8}
// h stored transposed: hT[(dir*2+buf)*320*64 + k*64 + b]
__global__ __launch_bounds__(256)
void gru_step(int s,
              const float* __restrict__ rk_fw, const float* __restrict__ rk_bw,
              const float* __restrict__ b_fw,  const float* __restrict__ b_bw,
              const float* __restrict__ mx_all,
              float* __restrict__ hT, float* __restrict__ y)
{
    const int dir = blockIdx.y;
    const int u0  = blockIdx.x * 4;
    const int tid = threadIdx.x;
    const int u   = tid & 3;
    const int bg  = (tid >> 2) & 7;
    const int ks  = tid >> 5;
    const int cur = s & 1;
    const int t   = dir ? (74 - s) : s;

    const float* hcur = hT + (size_t)(dir * 2 + cur) * (320 * 64);
    const float* RK   = (dir ? rk_bw : rk_fw) + (u0 + u);

    float acc[8][3];
#pragma unroll
    for (int i = 0; i < 8; i++) { acc[i][0] = acc[i][1] = acc[i][2] = 0.f; }

    const int kbse = ks * 40;
#pragma unroll 4
    for (int kk = 0; kk < 40; kk++) {
        int k = kbse + kk;
        const float4* hp = (const float4*)(hcur + (size_t)k * 64 + bg * 8);
        float4 a0 = hp[0], a1 = hp[1];
        const float* rp = RK + (size_t)k * 960;
        float r0 = rp[0], r1 = rp[320], r2 = rp[640];
        float ra[8] = {a0.x, a0.y, a0.z, a0.w, a1.x, a1.y, a1.z, a1.w};
#pragma unroll
        for (int i = 0; i < 8; i++) {
            acc[i][0] = fmaf(ra[i], r0, acc[i][0]);
            acc[i][1] = fmaf(ra[i], r1, acc[i][1]);
            acc[i][2] = fmaf(ra[i], r2, acc[i][2]);
        }
    }

    // reduce the 8 K-splits through smem; stride 13 keeps STS to <=2-way conflicts
    __shared__ float sm[8 * 64 * 13];
#pragma unroll
    for (int i = 0; i < 8; i++) {
        int b = bg * 8 + i;
        float* p = sm + (size_t)(ks * 64 + b) * 13 + u * 3;
        p[0] = acc[i][0]; p[1] = acc[i][1]; p[2] = acc[i][2];
    }
    __syncthreads();

    // gates: one thread per (b, unit)
    {
        int b  = tid >> 2;
        int uu = tid & 3;
        int c  = u0 + uu;
        float sz = 0.f, sr = 0.f, sh = 0.f;
#pragma unroll
        for (int z = 0; z < 8; z++) {
            const float* p = sm + (size_t)(z * 64 + b) * 13 + uu * 3;
            sz += p[0]; sr += p[1]; sh += p[2];
        }
        const float* mx = mx_all + (size_t)dir * (4800 * 960) + (size_t)(b * 75 + t) * 960;
        const float* br = (dir ? b_bw : b_fw) + 960;
        float hold = hcur[(size_t)c * 64 + b];
        float zg   = 1.f / (1.f + expf(-(mx[c]       + sz + br[c])));
        float rg   = 1.f / (1.f + expf(-(mx[320 + c] + sr + br[320 + c])));
        float cand = tanhf(mx[640 + c] + rg * (sh + br[640 + c]));
        float hn   = zg * hold + (1.f - zg) * cand;
        hT[(size_t)(dir * 2 + (cur ^ 1)) * (320 * 64) + (size_t)c * 64 + b] = hn;
        y[(size_t)b * 48000 + (size_t)t * 640 + dir * 320 + c] = hn;
    }
}

// ---------------- dense1 split-K reduce + bias + relu ----------------
__global__ __launch_bounds__(256)
void reduce_relu(const float* __restrict__ part, const float* __restrict__ bias,
                 float* __restrict__ out)
{
    int i = blockIdx.x * 256 + threadIdx.x;
    if (i >= 64 * 2000) return;
    float s = bias[i % 2000];
#pragma unroll 10
    for (int z = 0; z < KSPLIT_D1; z++) s += part[(size_t)z * 128000 + i];
    out[i] = fmaxf(s, 0.f);
}

// ---------------- dense2 + sigmoid ----------------
__global__ void dense2_kernel(const float* __restrict__ a1, const float* __restrict__ w2,
                              const float* __restrict__ b2, float* __restrict__ out)
{
    int n = blockIdx.x * 32 + threadIdx.x;
    int b = blockIdx.y * 8 + threadIdx.y;
    if (n >= 301) return;
    float acc = b2[n];
    const float* arow = a1 + (size_t)b * 2000;
#pragma unroll 4
    for (int k = 0; k < 2000; k++)
        acc = fmaf(arow[k], w2[(size_t)k * 301 + n], acc);
    out[(size_t)b * 301 + n] = 1.f / (1.f + expf(-acc));
}

// ---------------- launcher ----------------
extern "C" void kernel_launch(void* const* d_in, const int* in_sizes, int n_in,
                              void* d_out, int out_size)
{
    const float* inputs = (const float*)d_in[0];
    const float* conv_w = (const float*)d_in[1];
    const float* conv_b = (const float*)d_in[2];
    const float* fw_k   = (const float*)d_in[3];
    const float* fw_rk  = (const float*)d_in[4];
    const float* fw_b   = (const float*)d_in[5];
    const float* bw_k   = (const float*)d_in[6];
    const float* bw_rk  = (const float*)d_in[7];
    const float* bw_b   = (const float*)d_in[8];
    const float* w1     = (const float*)d_in[9];
    const float* b1     = (const float*)d_in[10];
    const float* w2     = (const float*)d_in[11];
    const float* b2     = (const float*)d_in[12];
    float* out = (float*)d_out;

    float *convout, *pooled, *mx, *hT, *ybuf, *part1, *a1;
    cudaGetSymbolAddress((void**)&convout, g_convout);
    cudaGetSymbolAddress((void**)&pooled,  g_pooled);
    cudaGetSymbolAddress((void**)&mx,      g_mx);
    cudaGetSymbolAddress((void**)&hT,      g_hT);
    cudaGetSymbolAddress((void**)&ybuf,    g_y);
    cudaGetSymbolAddress((void**)&part1,   g_part1);
    cudaGetSymbolAddress((void**)&a1,      g_a1);

    // 1) Conv1D + bias + relu as GEMM on the stride-4 im2col view (K=104)
    gemm8<128,128,1,1><<<dim3(3, 488, 1), 256>>>(
        inputs, conv_w, conv_b, convout, 62400, 320, 104, 4, 320, 320, 0);

    // 2) MaxPool(13)
    pool_kernel<<<(4800 * 320 + 255) / 256, 256>>>(convout, pooled);

    // 3) GRU input projections (+ input bias) for both directions
    gemm8<128,128,0,2><<<dim3(8, 38, 1), 256>>>(
        pooled, fw_k, fw_b, mx,               4800, 960, 320, 320, 960, 960, 0);
    gemm8<128,128,0,2><<<dim3(8, 38, 1), 256>>>(
        pooled, bw_k, bw_b, mx + 4800 * 960,  4800, 960, 320, 320, 960, 960, 0);

    // 4) zero transposed hidden state (both dirs, both buffers)
    cudaMemsetAsync(hT, 0, 4 * 320 * 64 * sizeof(float));

    // 5) 75 fused recurrent steps (one kernel per step)
    for (int s = 0; s < 75; s++) {
        gru_step<<<dim3(80, 2), 256>>>(s, fw_rk, bw_rk, fw_b, bw_b, mx, hT, ybuf);
    }

    // 6) Dense1 (64,48000)@(48000,2000): 50-way split-K, then reduce+bias+relu
    gemm8<64,256,0,0><<<dim3(8, 1, KSPLIT_D1), 256>>>(
        ybuf, w1, (const float*)0, part1, 64, 2000, 48000, 48000, 2000, 2000, 960);
    reduce_relu<<<(64 * 2000 + 255) / 256, 256>>>(part1, b1, a1);

    // 7) Dense2 + sigmoid
    dense2_kernel<<<dim3(10, 8), dim3(32, 8)>>>(a1, w2, b2, out);

    (void)in_sizes; (void)n_in; (void)out_size;
}

// round 11
// speedup vs baseline: 1.0946x; 1.0084x over previous
#include <cuda_runtime.h>
#include <math.h>
#include <stdint.h>

// ---------------- problem constants ----------------
// B=64, T_IN=1000, C_IN=4, F=320, K=26, POOL=13, T_CONV=975, T_POOL=75
// H=320, 3H=960, FLAT=48000, D1=2000, D2=301
static const int KSPLIT_D1 = 50;   // 48000 -> chunks of 960

// ---------------- device scratch (no allocations allowed) ----------------
__device__ float g_convout[62400 * 320];        // (B*975, 320) conv+relu
__device__ float g_pooled [4800 * 320];         // (B*75, 320)
__device__ float g_mx     [2 * 4800 * 960];     // x-projections fw|bw, row = b*75+t
__device__ float g_hT     [4 * 320 * 64];       // [dir][buf] hidden, TRANSPOSED [k][b]
__device__ float g_y      [64 * 48000];         // concat GRU output
__device__ float g_part1  [50 * 64 * 2000];     // dense1 split-K partials
__device__ float g_a1     [64 * 2000];          // dense1 activation

// ---------------- fp32 GEMM, 8x8 per thread, BK=8, 256 threads ----------------
// AMODE: 0 = A[row*lda + k]; 1 = conv im2col view A[(row/975)*4000 + (row%975)*4 + k]
// EPI:   0 raw, 1 bias+relu, 2 bias
// kchunk>0: split-K over blockIdx.z, partial at C + z*M*ldc (EPI ignored -> raw)
template<int BM,int BN,int AMODE,int EPI>
__global__ __launch_bounds__(256, 2)
void gemm8(const float* __restrict__ A, const float* __restrict__ Bm,
           const float* __restrict__ bias, float* __restrict__ C,
           int M, int N, int K, int lda, int ldb, int ldc, int kchunk)
{
    constexpr int TX = BN / 8, TY = BM / 8;
    static_assert(TX * TY == 256, "need 256 threads");
    __shared__ float sA[8][BM + 4];
    __shared__ float sB[8][BN];

    const int tid = threadIdx.x;
    const int tx = tid % TX, ty = tid / TX;
    const int m0 = blockIdx.y * BM;
    const int n0 = blockIdx.x * BN;

    int kb = 0, ke = K;
    float* Cout = C;
    if (kchunk > 0) {
        kb = blockIdx.z * kchunk;
        ke = kb + kchunk;              // callers guarantee K % kchunk == 0
        Cout = C + (size_t)blockIdx.z * (size_t)M * (size_t)ldc;
    }

    // ---- A loader mapping (row fixed across k-tiles) ----
    int alr, alk;
    if constexpr (BM == 128) { alr = tid >> 1; alk = (tid & 1) * 4; }
    else                     { alr = tid >> 2; alk = (tid & 3) * 2; }
    const int arow = m0 + alr;
    const bool aval = arow < M;
    size_t abase;
    if (AMODE == 1) abase = aval ? (size_t)(arow / 975) * 4000 + (size_t)(arow % 975) * 4 : 0;
    else            abase = aval ? (size_t)arow * (size_t)lda : 0;

    // ---- B loader mapping ----
    const int blk = tid >> 5;            // 0..7
    const int blc = (tid & 31) * 4;      // 0..124
    const bool fullN = (n0 + BN <= N);

    float acc[8][8];
#pragma unroll
    for (int i = 0; i < 8; i++)
#pragma unroll
        for (int j = 0; j < 8; j++) acc[i][j] = 0.f;

    for (int k0 = kb; k0 < ke; k0 += 8) {
        // stage A (transposed)
        if constexpr (BM == 128) {
            float4 v = aval ? *(const float4*)(A + abase + k0 + alk)
                            : make_float4(0.f, 0.f, 0.f, 0.f);
            sA[alk + 0][alr] = v.x; sA[alk + 1][alr] = v.y;
            sA[alk + 2][alr] = v.z; sA[alk + 3][alr] = v.w;
        } else {
            float2 v = aval ? *(const float2*)(A + abase + k0 + alk)
                            : make_float2(0.f, 0.f);
            sA[alk + 0][alr] = v.x; sA[alk + 1][alr] = v.y;
        }
        // stage B
        {
            const float* bp = Bm + (size_t)(k0 + blk) * (size_t)ldb + n0 + blc;
            if (fullN) {
                *(float4*)&sB[blk][blc] = *(const float4*)bp;
                if constexpr (BN == 256)
                    *(float4*)&sB[blk][blc + 128] = *(const float4*)(bp + 128);
            } else {
#pragma unroll
                for (int j = 0; j < 4; j++)
                    sB[blk][blc + j] = (n0 + blc + j < N) ? bp[j] : 0.f;
                if constexpr (BN == 256) {
#pragma unroll
                    for (int j = 0; j < 4; j++)
                        sB[blk][blc + 128 + j] = (n0 + blc + 128 + j < N) ? bp[128 + j] : 0.f;
                }
            }
        }
        __syncthreads();

#pragma unroll
        for (int kk = 0; kk < 8; kk++) {
            float4 a0 = *(const float4*)&sA[kk][ty * 8];
            float4 a1 = *(const float4*)&sA[kk][ty * 8 + 4];
            float4 b0 = *(const float4*)&sB[kk][tx * 8];
            float4 b1 = *(const float4*)&sB[kk][tx * 8 + 4];
            float ra[8] = {a0.x, a0.y, a0.z, a0.w, a1.x, a1.y, a1.z, a1.w};
            float rb[8] = {b0.x, b0.y, b0.z, b0.w, b1.x, b1.y, b1.z, b1.w};
#pragma unroll
            for (int i = 0; i < 8; i++)
#pragma unroll
                for (int j = 0; j < 8; j++)
                    acc[i][j] = fmaf(ra[i], rb[j], acc[i][j]);
        }
        __syncthreads();
    }

#pragma unroll
    for (int i = 0; i < 8; i++) {
        int row = m0 + ty * 8 + i;
        if (row >= M) continue;
        float* crow = Cout + (size_t)row * (size_t)ldc;
#pragma unroll
        for (int j = 0; j < 8; j++) {
            int col = n0 + tx * 8 + j;
            if (col >= N) continue;
            float v = acc[i][j];
            if (kchunk == 0) {
                if (EPI == 1)      v = fmaxf(v + bias[col], 0.f);
                else if (EPI == 2) v = v + bias[col];
            }
            crow[col] = v;
        }
    }
}

// ---------------- maxpool over 13 conv rows ----------------
__global__ __launch_bounds__(256)
void pool_kernel(const float* __restrict__ conv, float* __restrict__ pooled)
{
    int idx = blockIdx.x * 256 + threadIdx.x;
    if (idx >= 4800 * 320) return;
    int f = idx % 320;
    int bp = idx / 320;
    int b = bp / 75, p = bp % 75;
    const float* src = conv + ((size_t)(b * 975 + p * 13)) * 320 + f;
    float m = src[0];
#pragma unroll
    for (int q = 1; q < 13; q++) m = fmaxf(m, src[(size_t)q * 320]);
    pooled[idx] = m;
}

// ---------------- fused GRU step: recurrent GEMM + gates in ONE kernel ----------------
// grid (80, 2): block = (dir, 4 units); 256 threads = {u:4} x {bg:8} x {ks:8}
// h stored transposed: hT[(dir*2+buf)*320*64 + k*64 + b]
__global__ __launch_bounds__(256)
void gru_step(int s,
              const float* __restrict__ rk_fw, const float* __restrict__ rk_bw,
              const float* __restrict__ b_fw,  const float* __restrict__ b_bw,
              const float* __restrict__ mx_all,
              float* __restrict__ hT, float* __restrict__ y)
{
    const int dir = blockIdx.y;
    const int u0  = blockIdx.x * 4;
    const int tid = threadIdx.x;
    const int u   = tid & 3;
    const int bg  = (tid >> 2) & 7;
    const int ks  = tid >> 5;
    const int cur = s & 1;
    const int t   = dir ? (74 - s) : s;

    const float* hcur = hT + (size_t)(dir * 2 + cur) * (320 * 64);
    const float* RK   = (dir ? rk_bw : rk_fw) + (u0 + u);

    float acc[8][3];
#pragma unroll
    for (int i = 0; i < 8; i++) { acc[i][0] = acc[i][1] = acc[i][2] = 0.f; }

    const int kbse = ks * 40;
#pragma unroll 4
    for (int kk = 0; kk < 40; kk++) {
        int k = kbse + kk;
        const float4* hp = (const float4*)(hcur + (size_t)k * 64 + bg * 8);
        float4 a0 = hp[0], a1 = hp[1];
        const float* rp = RK + (size_t)k * 960;
        float r0 = rp[0], r1 = rp[320], r2 = rp[640];
        float ra[8] = {a0.x, a0.y, a0.z, a0.w, a1.x, a1.y, a1.z, a1.w};
#pragma unroll
        for (int i = 0; i < 8; i++) {
            acc[i][0] = fmaf(ra[i], r0, acc[i][0]);
            acc[i][1] = fmaf(ra[i], r1, acc[i][1]);
            acc[i][2] = fmaf(ra[i], r2, acc[i][2]);
        }
    }

    // reduce the 8 K-splits through smem; stride 13 keeps STS to <=2-way conflicts
    __shared__ float sm[8 * 64 * 13];
#pragma unroll
    for (int i = 0; i < 8; i++) {
        int b = bg * 8 + i;
        float* p = sm + (size_t)(ks * 64 + b) * 13 + u * 3;
        p[0] = acc[i][0]; p[1] = acc[i][1]; p[2] = acc[i][2];
    }
    __syncthreads();

    // gates: one thread per (b, unit)
    {
        int b  = tid >> 2;
        int uu = tid & 3;
        int c  = u0 + uu;
        float sz = 0.f, sr = 0.f, sh = 0.f;
#pragma unroll
        for (int z = 0; z < 8; z++) {
            const float* p = sm + (size_t)(z * 64 + b) * 13 + uu * 3;
            sz += p[0]; sr += p[1]; sh += p[2];
        }
        const float* mx = mx_all + (size_t)dir * (4800 * 960) + (size_t)(b * 75 + t) * 960;
        const float* br = (dir ? b_bw : b_fw) + 960;
        float hold = hcur[(size_t)c * 64 + b];
        float zg   = 1.f / (1.f + expf(-(mx[c]       + sz + br[c])));
        float rg   = 1.f / (1.f + expf(-(mx[320 + c] + sr + br[320 + c])));
        float cand = tanhf(mx[640 + c] + rg * (sh + br[640 + c]));
        float hn   = zg * hold + (1.f - zg) * cand;
        hT[(size_t)(dir * 2 + (cur ^ 1)) * (320 * 64) + (size_t)c * 64 + b] = hn;
        y[(size_t)b * 48000 + (size_t)t * 640 + dir * 320 + c] = hn;
    }
}

// ---------------- dense1 split-K reduce + bias + relu ----------------
__global__ __launch_bounds__(256)
void reduce_relu(const float* __restrict__ part, const float* __restrict__ bias,
                 float* __restrict__ out)
{
    int i = blockIdx.x * 256 + threadIdx.x;
    if (i >= 64 * 2000) return;
    float s = bias[i % 2000];
#pragma unroll 10
    for (int z = 0; z < KSPLIT_D1; z++) s += part[(size_t)z * 128000 + i];
    out[i] = fmaxf(s, 0.f);
}

// ---------------- dense2 + sigmoid ----------------
__global__ void dense2_kernel(const float* __restrict__ a1, const float* __restrict__ w2,
                              const float* __restrict__ b2, float* __restrict__ out)
{
    int n = blockIdx.x * 32 + threadIdx.x;
    int b = blockIdx.y * 8 + threadIdx.y;
    if (n >= 301) return;
    float acc = b2[n];
    const float* arow = a1 + (size_t)b * 2000;
#pragma unroll 4
    for (int k = 0; k < 2000; k++)
        acc = fmaf(arow[k], w2[(size_t)k * 301 + n], acc);
    out[(size_t)b * 301 + n] = 1.f / (1.f + expf(-acc));
}

// ---------------- launcher ----------------
extern "C" void kernel_launch(void* const* d_in, const int* in_sizes, int n_in,
                              void* d_out, int out_size)
{
    const float* inputs = (const float*)d_in[0];
    const float* conv_w = (const float*)d_in[1];
    const float* conv_b = (const float*)d_in[2];
    const float* fw_k   = (const float*)d_in[3];
    const float* fw_rk  = (const float*)d_in[4];
    const float* fw_b   = (const float*)d_in[5];
    const float* bw_k   = (const float*)d_in[6];
    const float* bw_rk  = (const float*)d_in[7];
    const float* bw_b   = (const float*)d_in[8];
    const float* w1     = (const float*)d_in[9];
    const float* b1     = (const float*)d_in[10];
    const float* w2     = (const float*)d_in[11];
    const float* b2     = (const float*)d_in[12];
    float* out = (float*)d_out;

    float *convout, *pooled, *mx, *hT, *ybuf, *part1, *a1;
    cudaGetSymbolAddress((void**)&convout, g_convout);
    cudaGetSymbolAddress((void**)&pooled,  g_pooled);
    cudaGetSymbolAddress((void**)&mx,      g_mx);
    cudaGetSymbolAddress((void**)&hT,      g_hT);
    cudaGetSymbolAddress((void**)&ybuf,    g_y);
    cudaGetSymbolAddress((void**)&part1,   g_part1);
    cudaGetSymbolAddress((void**)&a1,      g_a1);

    // 1) Conv1D + bias + relu as GEMM on the stride-4 im2col view (K=104)
    gemm8<128,128,1,1><<<dim3(3, 488, 1), 256>>>(
        inputs, conv_w, conv_b, convout, 62400, 320, 104, 4, 320, 320, 0);

    // 2) MaxPool(13)
    pool_kernel<<<(4800 * 320 + 255) / 256, 256>>>(convout, pooled);

    // 3) GRU input projections (+ input bias) for both directions
    gemm8<128,128,0,2><<<dim3(8, 38, 1), 256>>>(
        pooled, fw_k, fw_b, mx,               4800, 960, 320, 320, 960, 960, 0);
    gemm8<128,128,0,2><<<dim3(8, 38, 1), 256>>>(
        pooled, bw_k, bw_b, mx + 4800 * 960,  4800, 960, 320, 320, 960, 960, 0);

    // 4) zero transposed hidden state (both dirs, both buffers)
    cudaMemsetAsync(hT, 0, 4 * 320 * 64 * sizeof(float));

    // 5) 75 fused recurrent steps (one kernel per step)
    for (int s = 0; s < 75; s++) {
        gru_step<<<dim3(80, 2), 256>>>(s, fw_rk, bw_rk, fw_b, bw_b, mx, hT, ybuf);
    }

    // 6) Dense1 (64,48000)@(48000,2000): 50-way split-K, then reduce+bias+relu
    gemm8<64,256,0,0><<<dim3(8, 1, KSPLIT_D1), 256>>>(
        ybuf, w1, (const float*)0, part1, 64, 2000, 48000, 48000, 2000, 2000, 960);
    reduce_relu<<<(64 * 2000 + 255) / 256, 256>>>(part1, b1, a1);

    // 7) Dense2 + sigmoid
    dense2_kernel<<<dim3(10, 8), dim3(32, 8)>>>(a1, w2, b2, out);

    (void)in_sizes; (void)n_in; (void)out_size;
}